// round 1
// baseline (speedup 1.0000x reference)
#include <cuda_runtime.h>
#include <cstdint>

// Grid is 128^3
#define GRID_N (128*128*128)   // 2,097,152
#define SCAN_BLOCKS 1024       // 1024 blocks * 256 threads * 8 flags = 2,097,152

__device__ float g_density[GRID_N];
__device__ __align__(8) unsigned char g_active[GRID_N];
__device__ unsigned int g_blocksums[SCAN_BLOCKS];
__device__ unsigned int g_blockoffs[SCAN_BLOCKS];
__device__ unsigned int g_count;
__device__ unsigned int g_cells[GRID_N];

// ---------------------------------------------------------------------------
__global__ void zero_kernel() {
    int i = blockIdx.x * blockDim.x + threadIdx.x;
    if (i < GRID_N) {
        g_density[i] = 0.0f;
        g_active[i] = 0;
    }
}

// Scatter point features into density grid + mark active (3x3x3 neighborhood)
__global__ void scatter_kernel(const int* __restrict__ idx,
                               const float* __restrict__ feat, int n) {
    int i = blockIdx.x * blockDim.x + threadIdx.x;
    if (i >= n) return;
    int x = idx[3*i], y = idx[3*i+1], z = idx[3*i+2];
    unsigned lin = (x << 14) | (y << 7) | z;
    atomicAdd(&g_density[lin], feat[i]);
    #pragma unroll
    for (int di = -1; di <= 1; di++)
        #pragma unroll
        for (int dj = -1; dj <= 1; dj++)
            #pragma unroll
            for (int dk = -1; dk <= 1; dk++) {
                int nx = x + di, ny = y + dj, nz = z + dk;
                if ((unsigned)nx < 128u && (unsigned)ny < 128u && (unsigned)nz < 128u)
                    g_active[(nx << 14) | (ny << 7) | nz] = 1;  // racy stores of 1: fine
            }
}

// ---- prefix scan over 2M flags: 3 kernels -------------------------------
__global__ void scan1_kernel() {
    int base = blockIdx.x * 2048 + threadIdx.x * 8;
    unsigned long long v = *(const unsigned long long*)(g_active + base);
    unsigned s = (unsigned)((v * 0x0101010101010101ULL) >> 56);
    #pragma unroll
    for (int o = 16; o; o >>= 1) s += __shfl_down_sync(0xFFFFFFFFu, s, o);
    __shared__ unsigned ws[8];
    if ((threadIdx.x & 31) == 0) ws[threadIdx.x >> 5] = s;
    __syncthreads();
    if (threadIdx.x == 0) {
        unsigned t = 0;
        #pragma unroll
        for (int i = 0; i < 8; i++) t += ws[i];
        g_blocksums[blockIdx.x] = t;
    }
}

__global__ void scan2_kernel() {
    __shared__ unsigned sh[SCAN_BLOCKS];
    unsigned v = g_blocksums[threadIdx.x];
    sh[threadIdx.x] = v;
    __syncthreads();
    for (int o = 1; o < SCAN_BLOCKS; o <<= 1) {
        unsigned t = (threadIdx.x >= (unsigned)o) ? sh[threadIdx.x - o] : 0u;
        __syncthreads();
        sh[threadIdx.x] += t;
        __syncthreads();
    }
    g_blockoffs[threadIdx.x] = sh[threadIdx.x] - v;  // exclusive
    if (threadIdx.x == SCAN_BLOCKS - 1) g_count = sh[SCAN_BLOCKS - 1];
}

__global__ void scan3_kernel() {
    int base = blockIdx.x * 2048 + threadIdx.x * 8;
    unsigned long long v = *(const unsigned long long*)(g_active + base);
    unsigned s = (unsigned)((v * 0x0101010101010101ULL) >> 56);
    unsigned lane = threadIdx.x & 31, wid = threadIdx.x >> 5;
    unsigned incl = s;
    #pragma unroll
    for (int o = 1; o < 32; o <<= 1) {
        unsigned t = __shfl_up_sync(0xFFFFFFFFu, incl, o);
        if (lane >= (unsigned)o) incl += t;
    }
    unsigned excl = incl - s;
    __shared__ unsigned ws[8];
    if (lane == 31) ws[wid] = incl;
    __syncthreads();
    unsigned woff = 0;
    for (unsigned i = 0; i < wid; i++) woff += ws[i];
    unsigned pos = g_blockoffs[blockIdx.x] + woff + excl;
    #pragma unroll
    for (int i = 0; i < 8; i++) {
        if ((v >> (i * 8)) & 1ULL) g_cells[pos++] = (unsigned)(base + i);
    }
}

// ---- output writers ------------------------------------------------------
__global__ void uniq_kernel(float* __restrict__ out, int rows) {
    int r = blockIdx.x * blockDim.x + threadIdx.x;
    if (r >= rows) return;
    unsigned M = g_count;
    float fx = 128.0f, fy = 128.0f, fz = 128.0f;
    if (r < (int)M) {
        unsigned lin = g_cells[r];
        fx = (float)(lin >> 14);
        fy = (float)((lin >> 7) & 127u);
        fz = (float)(lin & 127u);
    }
    out[3*r + 0] = fx;
    out[3*r + 1] = fy;
    out[3*r + 2] = fz;
}

__global__ void __launch_bounds__(256)
feat_kernel(const float* __restrict__ kw, float* __restrict__ out, int rows) {
    __shared__ float Ks[27 * 64];
    for (int i = threadIdx.x; i < 27 * 64; i += blockDim.x) Ks[i] = kw[i];
    __syncthreads();
    int r = blockIdx.x * blockDim.x + threadIdx.x;
    if (r >= rows) return;
    float4* o = (float4*)(out + (size_t)r * 64);
    unsigned M = g_count;
    if (r >= (int)M) {
        float4 z4 = make_float4(0.f, 0.f, 0.f, 0.f);
        #pragma unroll
        for (int i = 0; i < 16; i++) o[i] = z4;
        return;
    }
    unsigned lin = g_cells[r];
    int x = lin >> 14, y = (lin >> 7) & 127, z = lin & 127;
    float acc[64];
    #pragma unroll
    for (int j = 0; j < 64; j++) acc[j] = 0.0f;
    #pragma unroll 1
    for (int t = 0; t < 27; t++) {
        int di = t / 9 - 1, dj = (t / 3) % 3 - 1, dk = t % 3 - 1;
        int nx = x + di, ny = y + dj, nz = z + dk;
        bool ok = (unsigned)nx < 128u && (unsigned)ny < 128u && (unsigned)nz < 128u;
        float d = ok ? g_density[(nx << 14) | (ny << 7) | nz] : 0.0f;
        const float4* K4 = (const float4*)(Ks + t * 64);
        #pragma unroll
        for (int i = 0; i < 16; i++) {
            float4 kv = K4[i];
            acc[4*i+0] = fmaf(d, kv.x, acc[4*i+0]);
            acc[4*i+1] = fmaf(d, kv.y, acc[4*i+1]);
            acc[4*i+2] = fmaf(d, kv.z, acc[4*i+2]);
            acc[4*i+3] = fmaf(d, kv.w, acc[4*i+3]);
        }
    }
    #pragma unroll
    for (int i = 0; i < 16; i++)
        o[i] = make_float4(acc[4*i], acc[4*i+1], acc[4*i+2], acc[4*i+3]);
}

// ---------------------------------------------------------------------------
extern "C" void kernel_launch(void* const* d_in, const int* in_sizes, int n_in,
                              void* d_out, int out_size) {
    const int*   indices  = (const int*)d_in[0];    // [N,3] int32
    const float* features = (const float*)d_in[1];  // [N,1] float32
    const float* kw       = (const float*)d_in[2];  // [3,3,3,1,64] float32

    int n = in_sizes[0] / 3;
    int rows = n * 27;
    float* out = (float*)d_out;

    zero_kernel<<<(GRID_N + 255) / 256, 256>>>();
    scatter_kernel<<<(n + 255) / 256, 256>>>(indices, features, n);
    scan1_kernel<<<SCAN_BLOCKS, 256>>>();
    scan2_kernel<<<1, SCAN_BLOCKS>>>();
    scan3_kernel<<<SCAN_BLOCKS, 256>>>();

    int rblocks = (rows + 255) / 256;
    if (out_size == rows * 64) {
        // only out_feat compared
        feat_kernel<<<rblocks, 256>>>(kw, out, rows);
    } else if (out_size == rows * 3) {
        // only uniq compared
        uniq_kernel<<<rblocks, 256>>>(out, rows);
    } else {
        // assume concatenated [uniq.ravel() | out_feat.ravel()] as float32
        uniq_kernel<<<rblocks, 256>>>(out, rows);
        feat_kernel<<<rblocks, 256>>>(kw, out + (size_t)rows * 3, rows);
    }
}

// round 2
// speedup vs baseline: 1.4984x; 1.4984x over previous
#include <cuda_runtime.h>
#include <cstdint>

// Grid is 128^3
#define GRID_N (128*128*128)   // 2,097,152
#define SCAN_BLOCKS 1024       // 1024 blocks * 256 threads * 8 flags = 2,097,152

__device__ float g_density[GRID_N];
__device__ __align__(8) unsigned char g_active[GRID_N];
__device__ unsigned int g_blocksums[SCAN_BLOCKS];
__device__ unsigned int g_blockoffs[SCAN_BLOCKS];
__device__ unsigned int g_count;
__device__ unsigned int g_cells[GRID_N];

// ---------------------------------------------------------------------------
// Scatter point features into density grid + mark active (3x3x3 neighborhood)
__global__ void scatter_kernel(const int* __restrict__ idx,
                               const float* __restrict__ feat, int n) {
    int i = blockIdx.x * blockDim.x + threadIdx.x;
    if (i >= n) return;
    int x = idx[3*i], y = idx[3*i+1], z = idx[3*i+2];
    unsigned lin = (x << 14) | (y << 7) | z;
    atomicAdd(&g_density[lin], feat[i]);
    #pragma unroll
    for (int di = -1; di <= 1; di++)
        #pragma unroll
        for (int dj = -1; dj <= 1; dj++)
            #pragma unroll
            for (int dk = -1; dk <= 1; dk++) {
                int nx = x + di, ny = y + dj, nz = z + dk;
                if ((unsigned)nx < 128u && (unsigned)ny < 128u && (unsigned)nz < 128u)
                    g_active[(nx << 14) | (ny << 7) | nz] = 1;  // racy stores of 1: fine
            }
}

// ---- prefix scan over 2M flags: 3 kernels -------------------------------
__global__ void scan1_kernel() {
    int base = blockIdx.x * 2048 + threadIdx.x * 8;
    unsigned long long v = *(const unsigned long long*)(g_active + base);
    unsigned s = (unsigned)((v * 0x0101010101010101ULL) >> 56);
    #pragma unroll
    for (int o = 16; o; o >>= 1) s += __shfl_down_sync(0xFFFFFFFFu, s, o);
    __shared__ unsigned ws[8];
    if ((threadIdx.x & 31) == 0) ws[threadIdx.x >> 5] = s;
    __syncthreads();
    if (threadIdx.x == 0) {
        unsigned t = 0;
        #pragma unroll
        for (int i = 0; i < 8; i++) t += ws[i];
        g_blocksums[blockIdx.x] = t;
    }
}

__global__ void scan2_kernel() {
    __shared__ unsigned sh[SCAN_BLOCKS];
    unsigned v = g_blocksums[threadIdx.x];
    sh[threadIdx.x] = v;
    __syncthreads();
    for (int o = 1; o < SCAN_BLOCKS; o <<= 1) {
        unsigned t = (threadIdx.x >= (unsigned)o) ? sh[threadIdx.x - o] : 0u;
        __syncthreads();
        sh[threadIdx.x] += t;
        __syncthreads();
    }
    g_blockoffs[threadIdx.x] = sh[threadIdx.x] - v;  // exclusive
    if (threadIdx.x == SCAN_BLOCKS - 1) g_count = sh[SCAN_BLOCKS - 1];
}

__global__ void scan3_kernel() {
    int base = blockIdx.x * 2048 + threadIdx.x * 8;
    unsigned long long v = *(const unsigned long long*)(g_active + base);
    unsigned s = (unsigned)((v * 0x0101010101010101ULL) >> 56);
    unsigned lane = threadIdx.x & 31, wid = threadIdx.x >> 5;
    unsigned incl = s;
    #pragma unroll
    for (int o = 1; o < 32; o <<= 1) {
        unsigned t = __shfl_up_sync(0xFFFFFFFFu, incl, o);
        if (lane >= (unsigned)o) incl += t;
    }
    unsigned excl = incl - s;
    __shared__ unsigned ws[8];
    if (lane == 31) ws[wid] = incl;
    __syncthreads();
    unsigned woff = 0;
    for (unsigned i = 0; i < wid; i++) woff += ws[i];
    unsigned pos = g_blockoffs[blockIdx.x] + woff + excl;
    #pragma unroll
    for (int i = 0; i < 8; i++) {
        if ((v >> (i * 8)) & 1ULL) g_cells[pos++] = (unsigned)(base + i);
    }
}

// ---- fused output writer: coords + conv features ------------------------
// Packed dual-fp32 FMA (sm_100+): d = a*b+d on 2 lanes per instruction.
__device__ __forceinline__ void fma_x2(unsigned long long& d,
                                       unsigned long long a,
                                       unsigned long long b) {
    asm("fma.rn.f32x2 %0, %1, %2, %0;" : "+l"(d) : "l"(a), "l"(b));
}

__global__ void __launch_bounds__(256)
feat_kernel(const float* __restrict__ kw,
            float* __restrict__ outc,   // [rows,3] coords (may be null)
            float* __restrict__ outf,   // [rows,64] features (may be null)
            int rows) {
    __shared__ float Ks[27 * 64];
    for (int i = threadIdx.x; i < 27 * 64; i += blockDim.x) Ks[i] = kw[i];
    __syncthreads();
    int r = blockIdx.x * blockDim.x + threadIdx.x;
    if (r >= rows) return;
    unsigned M = g_count;

    if (r >= (int)M) {
        if (outc) {
            outc[3*r + 0] = 128.0f;
            outc[3*r + 1] = 128.0f;
            outc[3*r + 2] = 128.0f;
        }
        if (outf) {
            float4* o = (float4*)(outf + (size_t)r * 64);
            float4 z4 = make_float4(0.f, 0.f, 0.f, 0.f);
            #pragma unroll
            for (int i = 0; i < 16; i++) o[i] = z4;
        }
        return;
    }

    unsigned lin = g_cells[r];
    int x = lin >> 14, y = (lin >> 7) & 127, z = lin & 127;
    if (outc) {
        outc[3*r + 0] = (float)x;
        outc[3*r + 1] = (float)y;
        outc[3*r + 2] = (float)z;
    }
    if (!outf) return;

    unsigned long long acc[32];
    #pragma unroll
    for (int j = 0; j < 32; j++) acc[j] = 0ULL;

    #pragma unroll 1
    for (int t = 0; t < 27; t++) {
        int di = t / 9 - 1, dj = (t / 3) % 3 - 1, dk = t % 3 - 1;
        int nx = x + di, ny = y + dj, nz = z + dk;
        bool ok = (unsigned)nx < 128u && (unsigned)ny < 128u && (unsigned)nz < 128u;
        float d = ok ? g_density[(nx << 14) | (ny << 7) | nz] : 0.0f;
        unsigned du = __float_as_uint(d);
        unsigned long long dd = ((unsigned long long)du << 32) | du;  // (d,d)
        const ulonglong2* K2 = (const ulonglong2*)(Ks + t * 64);
        #pragma unroll
        for (int i = 0; i < 16; i++) {
            ulonglong2 kv = K2[i];               // 4 kernel floats (2 packed pairs)
            fma_x2(acc[2*i + 0], kv.x, dd);
            fma_x2(acc[2*i + 1], kv.y, dd);
        }
    }

    ulonglong2* o = (ulonglong2*)(outf + (size_t)r * 64);
    #pragma unroll
    for (int i = 0; i < 16; i++) {
        ulonglong2 v; v.x = acc[2*i]; v.y = acc[2*i + 1];
        o[i] = v;
    }
}

// ---------------------------------------------------------------------------
extern "C" void kernel_launch(void* const* d_in, const int* in_sizes, int n_in,
                              void* d_out, int out_size) {
    const int*   indices  = (const int*)d_in[0];    // [N,3] int32
    const float* features = (const float*)d_in[1];  // [N,1] float32
    const float* kw       = (const float*)d_in[2];  // [3,3,3,1,64] float32

    int n = in_sizes[0] / 3;
    int rows = n * 27;
    float* out = (float*)d_out;

    // zero density + active via memset nodes
    void* p_density = nullptr;
    void* p_active  = nullptr;
    cudaGetSymbolAddress(&p_density, g_density);
    cudaGetSymbolAddress(&p_active,  g_active);
    cudaMemsetAsync(p_density, 0, GRID_N * sizeof(float));
    cudaMemsetAsync(p_active,  0, GRID_N);

    scatter_kernel<<<(n + 255) / 256, 256>>>(indices, features, n);
    scan1_kernel<<<SCAN_BLOCKS, 256>>>();
    scan2_kernel<<<1, SCAN_BLOCKS>>>();
    scan3_kernel<<<SCAN_BLOCKS, 256>>>();

    int rblocks = (rows + 255) / 256;
    if (out_size == rows * 64) {
        feat_kernel<<<rblocks, 256>>>(kw, nullptr, out, rows);
    } else if (out_size == rows * 3) {
        feat_kernel<<<rblocks, 256>>>(kw, out, nullptr, rows);
    } else {
        // concatenated [uniq.ravel() | out_feat.ravel()] as float32
        feat_kernel<<<rblocks, 256>>>(kw, out, out + (size_t)rows * 3, rows);
    }
}